// round 4
// baseline (speedup 1.0000x reference)
#include <cuda_runtime.h>
#include <cuda_bf16.h>
#include <cstdint>

#define CH    64
#define EPSV  1e-5f
#define MAXN  100000
#define MAXK  27

// ================= scratch (__device__ globals, alloc-free) =================
__device__ float g_buf1[MAXN * CH];      // conv1 raw output (fp32)
__device__ float g_buf2[MAXN * CH];      // conv2 raw output (fp32)
__device__ float g_stats[256];           // [sum1, sumsq1, sum2, sumsq2]
__device__ float g_sb[256];              // [scale1, shift1, scale2, shift2]
__device__ __align__(16) __nv_bfloat16 g_fhi[MAXN * CH];
__device__ __align__(16) __nv_bfloat16 g_flo[MAXN * CH];
// W pre-packed into mma.sync B-fragment order (column-permuted): [k][2048] u32
__device__ __align__(16) uint32_t g_WfH1[MAXK * 2048];
__device__ __align__(16) uint32_t g_WfL1[MAXK * 2048];
__device__ __align__(16) uint32_t g_WfH2[MAXK * 2048];
__device__ __align__(16) uint32_t g_WfL2[MAXK * 2048];

// ================= helpers =================
__device__ __forceinline__ uint32_t smem_u32(const void* p) {
    uint32_t a;
    asm("{ .reg .u64 t; cvta.to.shared.u64 t, %1; cvt.u32.u64 %0, t; }" : "=r"(a) : "l"(p));
    return a;
}

__device__ __forceinline__ void ldmatrix_x4(uint32_t* r, uint32_t addr) {
    asm volatile("ldmatrix.sync.aligned.m8n8.x4.shared.b16 {%0,%1,%2,%3}, [%4];"
                 : "=r"(r[0]), "=r"(r[1]), "=r"(r[2]), "=r"(r[3]) : "r"(addr));
}

__device__ __forceinline__ void mma16816(float* c, const uint32_t* a,
                                         uint32_t b0, uint32_t b1) {
    asm volatile(
        "mma.sync.aligned.m16n8k16.row.col.f32.bf16.bf16.f32 "
        "{%0,%1,%2,%3}, {%4,%5,%6,%7}, {%8,%9}, {%0,%1,%2,%3};"
        : "+f"(c[0]), "+f"(c[1]), "+f"(c[2]), "+f"(c[3])
        : "r"(a[0]), "r"(a[1]), "r"(a[2]), "r"(a[3]), "r"(b0), "r"(b1));
}

// SMEM layout for conv kernel (dynamic)
#define OFF_AH   0
#define OFF_AL   16384
#define OFF_BH   32768
#define OFF_BL   40960
#define OFF_IIDX 49152
#define OFF_OIDX 49664
#define SMEM_BYTES 50176

// ================= kernels =================

__global__ void zero_kernel(int total4)
{
    const float4 z = make_float4(0.f, 0.f, 0.f, 0.f);
    int i = blockIdx.x * blockDim.x + threadIdx.x;
    for (int j = i; j < total4; j += gridDim.x * blockDim.x) {
        reinterpret_cast<float4*>(g_buf1)[j] = z;
        reinterpret_cast<float4*>(g_buf2)[j] = z;
    }
    if (blockIdx.x == 0 && threadIdx.x < 64)
        reinterpret_cast<float4*>(g_stats)[threadIdx.x] = z;
}

// W[k][cin][cout] fp32 -> bf16 hi/lo split packed in mma B-fragment order,
// with output columns PERMUTED so that each lane's 4 accumulator values from
// an (even,odd) nt-tile pair hit 4 contiguous global columns (enables red.v4).
// u32 index i: reg = i&1, lane = (i>>1)&31, nt = (i>>6)&7, ks = i>>9
// k0 = ks*16 + (lane&3)*2 + reg*8 ; local col l = lane>>2
// source col n = 16*(nt>>1) + 4*(l>>1) + 2*(nt&1) + (l&1)
__global__ __launch_bounds__(256)
void prep_w_kernel(const float* __restrict__ W1, const float* __restrict__ W2, int K)
{
    const int k     = blockIdx.x;
    const int layer = blockIdx.y;
    const float* Wk = (layer ? W2 : W1) + (size_t)k * 4096;
    uint32_t* dh = (layer ? g_WfH2 : g_WfH1) + (size_t)k * 2048;
    uint32_t* dl = (layer ? g_WfL2 : g_WfL1) + (size_t)k * 2048;

    for (int i = threadIdx.x; i < 2048; i += 256) {
        const int reg  = i & 1;
        const int lane = (i >> 1) & 31;
        const int nt   = (i >> 6) & 7;
        const int ks   = i >> 9;
        const int k0   = ks * 16 + (lane & 3) * 2 + reg * 8;
        const int l    = lane >> 2;
        const int n    = 16 * (nt >> 1) + 4 * (l >> 1) + 2 * (nt & 1) + (l & 1);
        const float v0 = Wk[k0 * 64 + n];
        const float v1 = Wk[(k0 + 1) * 64 + n];
        const __nv_bfloat16 h0 = __float2bfloat16(v0);
        const __nv_bfloat16 h1 = __float2bfloat16(v1);
        const __nv_bfloat16 l0 = __float2bfloat16(v0 - __bfloat162float(h0));
        const __nv_bfloat16 l1 = __float2bfloat16(v1 - __bfloat162float(h1));
        dh[i] = (uint32_t)__bfloat16_as_ushort(h0)
              | ((uint32_t)__bfloat16_as_ushort(h1) << 16);
        dl[i] = (uint32_t)__bfloat16_as_ushort(l0)
              | ((uint32_t)__bfloat16_as_ushort(l1) << 16);
    }
}

// fp32 rows -> bf16 hi/lo split (optionally fused relu(bn) via sb scale/shift)
__global__ __launch_bounds__(256)
void prep_feat_kernel(const float* __restrict__ src, const float* __restrict__ sb,
                      int N)
{
    const int gid = blockIdx.x * blockDim.x + threadIdx.x;
    if (gid >= N * 8) return;
    const int row = gid >> 3;
    const int c0  = (gid & 7) * 8;

    const float4 v0 = reinterpret_cast<const float4*>(src + (size_t)row * 64 + c0)[0];
    const float4 v1 = reinterpret_cast<const float4*>(src + (size_t)row * 64 + c0)[1];
    float v[8] = {v0.x, v0.y, v0.z, v0.w, v1.x, v1.y, v1.z, v1.w};

    if (sb) {
        #pragma unroll
        for (int j = 0; j < 8; ++j)
            v[j] = fmaxf(fmaf(v[j], sb[c0 + j], sb[64 + c0 + j]), 0.f);
    }

    union { __nv_bfloat16 h[8]; uint4 u; } uh, ul;
    #pragma unroll
    for (int j = 0; j < 8; ++j) {
        const __nv_bfloat16 hi = __float2bfloat16(v[j]);
        uh.h[j] = hi;
        ul.h[j] = __float2bfloat16(v[j] - __bfloat162float(hi));
    }
    reinterpret_cast<uint4*>(g_fhi)[(size_t)row * 8 + (c0 >> 3)] = uh.u;
    reinterpret_cast<uint4*>(g_flo)[(size_t)row * 8 + (c0 >> 3)] = ul.u;
}

// gather -> mma.sync bf16-split -> red.v4 scatter
// 4 warps (128 threads) per block; each warp computes TWO 16-row tiles so each
// B-fragment LDS is reused twice (halves B shared-memory traffic vs 8 warps).
__global__ __launch_bounds__(128)
void conv_mma_kernel(const __nv_bfloat16* __restrict__ fhi,
                     const __nv_bfloat16* __restrict__ flo,
                     const uint32_t* __restrict__ WfH,
                     const uint32_t* __restrict__ WfL,
                     const int* __restrict__ in_maps,
                     const int* __restrict__ out_maps,
                     float* __restrict__ out,
                     int M)
{
    extern __shared__ char sm[];
    char*     Ah   = sm + OFF_AH;
    char*     Al   = sm + OFF_AL;
    uint32_t* BH   = reinterpret_cast<uint32_t*>(sm + OFF_BH);
    uint32_t* BL   = reinterpret_cast<uint32_t*>(sm + OFF_BL);
    int*      iidx = reinterpret_cast<int*>(sm + OFF_IIDX);
    int*      oidx = reinterpret_cast<int*>(sm + OFF_OIDX);

    const int t    = threadIdx.x;
    const int lane = t & 31;
    const int w    = t >> 5;
    const int k    = blockIdx.y;
    const int m0   = blockIdx.x * 128;

    // maps
    {
        const int m = m0 + t;
        iidx[t] = (m < M) ? in_maps [(size_t)k * M + m] : -1;
        oidx[t] = (m < M) ? out_maps[(size_t)k * M + m] : -1;
    }
    // B-fragment copy (4096 uint4 total across hi+lo)
    {
        const uint4* sh = reinterpret_cast<const uint4*>(WfH + (size_t)k * 2048);
        const uint4* sl = reinterpret_cast<const uint4*>(WfL + (size_t)k * 2048);
        #pragma unroll
        for (int i = 0; i < 4; ++i) {
            reinterpret_cast<uint4*>(BH)[t + i * 128] = sh[t + i * 128];
            reinterpret_cast<uint4*>(BL)[t + i * 128] = sl[t + i * 128];
        }
    }
    __syncthreads();

    // gather A (hi/lo), XOR-swizzled rows: chunk c of row r -> (c ^ (r&7))
    {
        const int row = t;                 // one row per thread
        const int src = iidx[row];
        const uint4 z = make_uint4(0, 0, 0, 0);
        #pragma unroll
        for (int c = 0; c < 8; ++c) {
            uint4 vh = z, vl = z;
            if (src >= 0) {
                vh = reinterpret_cast<const uint4*>(fhi)[(size_t)src * 8 + c];
                vl = reinterpret_cast<const uint4*>(flo)[(size_t)src * 8 + c];
            }
            const int d = row * 128 + ((c ^ (row & 7)) << 4);
            *reinterpret_cast<uint4*>(Ah + d) = vh;
            *reinterpret_cast<uint4*>(Al + d) = vl;
        }
    }
    __syncthreads();

    // MMA mainloop: warp w owns rows [w*32, w*32+32) as two 16-row tiles.
    float acc[2][8][4];
    #pragma unroll
    for (int rt = 0; rt < 2; ++rt)
        #pragma unroll
        for (int nt = 0; nt < 8; ++nt)
            #pragma unroll
            for (int j = 0; j < 4; ++j) acc[rt][nt][j] = 0.f;

    const uint32_t ahb = smem_u32(Ah);
    const uint32_t alb = smem_u32(Al);
    const int half = lane >> 4;

    #pragma unroll
    for (int ks = 0; ks < 4; ++ks) {
        uint32_t aH[2][4], aL[2][4];
        #pragma unroll
        for (int rt = 0; rt < 2; ++rt) {
            const int row = w * 32 + rt * 16 + (lane & 15);
            const int chunk = ks * 2 + half;
            const uint32_t off = row * 128 + ((chunk ^ (row & 7)) << 4);
            ldmatrix_x4(aH[rt], ahb + off);
            ldmatrix_x4(aL[rt], alb + off);
        }
        #pragma unroll
        for (int nt = 0; nt < 8; ++nt) {
            const int fi = ((ks * 8 + nt) * 32 + lane) * 2;
            const uint2 bh = *reinterpret_cast<const uint2*>(&BH[fi]);
            const uint2 bl = *reinterpret_cast<const uint2*>(&BL[fi]);
            #pragma unroll
            for (int rt = 0; rt < 2; ++rt) {
                mma16816(acc[rt][nt], aH[rt], bh.x, bh.y);
                mma16816(acc[rt][nt], aH[rt], bl.x, bl.y);
                mma16816(acc[rt][nt], aL[rt], bh.x, bh.y);
            }
        }
    }

    // scatter via red.v4: column permutation makes each lane's 4 values from
    // tiles (2p, 2p+1) land on contiguous global cols 16p + 4*(lane&3) .. +3
    #pragma unroll
    for (int rt = 0; rt < 2; ++rt) {
        const int r0 = w * 32 + rt * 16 + (lane >> 2);
        const int o0 = oidx[r0];
        const int o1 = oidx[r0 + 8];
        const int cb = 4 * (lane & 3);
        #pragma unroll
        for (int p = 0; p < 4; ++p) {
            const int col = 16 * p + cb;
            if (o0 >= 0) {
                asm volatile("red.global.add.v4.f32 [%0], {%1, %2, %3, %4};"
                    :: "l"(out + (size_t)o0 * 64 + col),
                       "f"(acc[rt][2*p][0]), "f"(acc[rt][2*p][1]),
                       "f"(acc[rt][2*p+1][0]), "f"(acc[rt][2*p+1][1]) : "memory");
            }
            if (o1 >= 0) {
                asm volatile("red.global.add.v4.f32 [%0], {%1, %2, %3, %4};"
                    :: "l"(out + (size_t)o1 * 64 + col),
                       "f"(acc[rt][2*p][2]), "f"(acc[rt][2*p][3]),
                       "f"(acc[rt][2*p+1][2]), "f"(acc[rt][2*p+1][3]) : "memory");
            }
        }
    }
}

// per-channel sum / sumsq
__global__ __launch_bounds__(256)
void stats_kernel(const float* __restrict__ x, int N, float* __restrict__ sums)
{
    const int t   = threadIdx.x;
    const int col = t & 63;
    const int rg  = t >> 6;
    float s = 0.f, ss = 0.f;
    for (int r = blockIdx.x * 4 + rg; r < N; r += gridDim.x * 4) {
        const float v = x[(size_t)r * 64 + col];
        s += v; ss += v * v;
    }
    __shared__ float sh[512];
    sh[t] = s; sh[256 + t] = ss;
    __syncthreads();
    if (t < 64) {
        float S  = sh[t]       + sh[t + 64]       + sh[t + 128]       + sh[t + 192];
        float SS = sh[256 + t] + sh[256 + t + 64] + sh[256 + t + 128] + sh[256 + t + 192];
        atomicAdd(&sums[t],      S);
        atomicAdd(&sums[64 + t], SS);
    }
}

__global__ void finalize_kernel(const float* __restrict__ sums,
                                const float* __restrict__ gamma,
                                const float* __restrict__ beta,
                                float invN, float* __restrict__ sb)
{
    const int t = threadIdx.x;
    const float mean = sums[t] * invN;
    const float var  = fmaxf(sums[64 + t] * invN - mean * mean, 0.f);
    const float s    = gamma[t] * rsqrtf(var + EPSV);
    sb[t]      = s;
    sb[64 + t] = beta[t] - mean * s;
}

__global__ __launch_bounds__(256)
void final_kernel(const float* __restrict__ conv2, const float* __restrict__ sb2,
                  const float* __restrict__ feat, float* __restrict__ out, int n4)
{
    int i = blockIdx.x * blockDim.x + threadIdx.x;
    for (int j = i; j < n4; j += gridDim.x * blockDim.x) {
        const float4 v = reinterpret_cast<const float4*>(conv2)[j];
        const float4 f = reinterpret_cast<const float4*>(feat)[j];
        const int c0 = (j & 15) * 4;
        float4 r;
        r.x = fmaxf(fmaf(v.x, sb2[c0 + 0], sb2[64 + c0 + 0]) + f.x, 0.f);
        r.y = fmaxf(fmaf(v.y, sb2[c0 + 1], sb2[64 + c0 + 1]) + f.y, 0.f);
        r.z = fmaxf(fmaf(v.z, sb2[c0 + 2], sb2[64 + c0 + 2]) + f.z, 0.f);
        r.w = fmaxf(fmaf(v.w, sb2[c0 + 3], sb2[64 + c0 + 3]) + f.w, 0.f);
        reinterpret_cast<float4*>(out)[j] = r;
    }
}

// ================= launcher =================
extern "C" void kernel_launch(void* const* d_in, const int* in_sizes, int n_in,
                              void* d_out, int out_size)
{
    const float* features = (const float*)d_in[0];
    const float* W1       = (const float*)d_in[1];
    const float* gamma1   = (const float*)d_in[2];
    const float* beta1    = (const float*)d_in[3];
    const float* W2       = (const float*)d_in[4];
    const float* gamma2   = (const float*)d_in[5];
    const float* beta2    = (const float*)d_in[6];
    const int*   in_maps  = (const int*)d_in[7];
    const int*   out_maps = (const int*)d_in[8];
    float*       out      = (float*)d_out;

    const int N = in_sizes[0] / CH;
    const int K = in_sizes[1] / (CH * CH);
    const int M = in_sizes[7] / K;

    float* buf1;  cudaGetSymbolAddress((void**)&buf1,  g_buf1);
    float* buf2;  cudaGetSymbolAddress((void**)&buf2,  g_buf2);
    float* stats; cudaGetSymbolAddress((void**)&stats, g_stats);
    float* sb;    cudaGetSymbolAddress((void**)&sb,    g_sb);
    __nv_bfloat16 *fhi, *flo;
    cudaGetSymbolAddress((void**)&fhi, g_fhi);
    cudaGetSymbolAddress((void**)&flo, g_flo);
    uint32_t *wh1, *wl1, *wh2, *wl2;
    cudaGetSymbolAddress((void**)&wh1, g_WfH1);
    cudaGetSymbolAddress((void**)&wl1, g_WfL1);
    cudaGetSymbolAddress((void**)&wh2, g_WfH2);
    cudaGetSymbolAddress((void**)&wl2, g_WfL2);

    cudaFuncSetAttribute(conv_mma_kernel,
                         cudaFuncAttributeMaxDynamicSharedMemorySize, SMEM_BYTES);

    const int total4 = N * (CH / 4);
    const float invN = 1.0f / (float)N;
    const dim3 convGrid((M + 127) / 128, K);
    const int pfBlocks = (N * 8 + 255) / 256;

    zero_kernel<<<1024, 256>>>(total4);
    prep_w_kernel<<<dim3(K, 2), 256>>>(W1, W2, K);

    // conv1
    prep_feat_kernel<<<pfBlocks, 256>>>(features, nullptr, N);
    conv_mma_kernel<<<convGrid, 128, SMEM_BYTES>>>(fhi, flo, wh1, wl1,
                                                   in_maps, out_maps, buf1, M);
    stats_kernel<<<512, 256>>>(buf1, N, stats);
    finalize_kernel<<<1, 64>>>(stats, gamma1, beta1, invN, sb);

    // conv2 (BN1+ReLU fused into split pass)
    prep_feat_kernel<<<pfBlocks, 256>>>(buf1, sb, N);
    conv_mma_kernel<<<convGrid, 128, SMEM_BYTES>>>(fhi, flo, wh2, wl2,
                                                   in_maps, out_maps, buf2, M);
    stats_kernel<<<512, 256>>>(buf2, N, stats + 128);
    finalize_kernel<<<1, 64>>>(stats + 128, gamma2, beta2, invN, sb + 128);

    final_kernel<<<1024, 256>>>(buf2, sb + 128, features, out, total4);
}

// round 5
// speedup vs baseline: 1.4167x; 1.4167x over previous
#include <cuda_runtime.h>
#include <cuda_bf16.h>
#include <cstdint>

#define CH    64
#define EPSV  1e-5f
#define MAXN  100000
#define MAXK  27

// ================= scratch (__device__ globals, alloc-free) =================
__device__ float g_buf1[MAXN * CH];      // conv1 raw output (fp32)
__device__ float g_buf2[MAXN * CH];      // conv2 raw output (fp32)
__device__ float g_stats[256];           // [sum1, sumsq1, sum2, sumsq2]
__device__ float g_sb[256];              // [scale1, shift1, scale2, shift2]
__device__ __align__(16) __nv_bfloat16 g_fhi[MAXN * CH];
__device__ __align__(16) __nv_bfloat16 g_flo[MAXN * CH];
// W pre-packed into mma.sync B-fragment order (column-permuted): [k][2048] u32
__device__ __align__(16) uint32_t g_WfH1[MAXK * 2048];
__device__ __align__(16) uint32_t g_WfL1[MAXK * 2048];
__device__ __align__(16) uint32_t g_WfH2[MAXK * 2048];
__device__ __align__(16) uint32_t g_WfL2[MAXK * 2048];

// ================= helpers =================
__device__ __forceinline__ uint32_t smem_u32(const void* p) {
    uint32_t a;
    asm("{ .reg .u64 t; cvta.to.shared.u64 t, %1; cvt.u32.u64 %0, t; }" : "=r"(a) : "l"(p));
    return a;
}

__device__ __forceinline__ void ldmatrix_x4(uint32_t* r, uint32_t addr) {
    asm volatile("ldmatrix.sync.aligned.m8n8.x4.shared.b16 {%0,%1,%2,%3}, [%4];"
                 : "=r"(r[0]), "=r"(r[1]), "=r"(r[2]), "=r"(r[3]) : "r"(addr));
}

__device__ __forceinline__ void mma16816(float* c, const uint32_t* a,
                                         uint32_t b0, uint32_t b1) {
    asm volatile(
        "mma.sync.aligned.m16n8k16.row.col.f32.bf16.bf16.f32 "
        "{%0,%1,%2,%3}, {%4,%5,%6,%7}, {%8,%9}, {%0,%1,%2,%3};"
        : "+f"(c[0]), "+f"(c[1]), "+f"(c[2]), "+f"(c[3])
        : "r"(a[0]), "r"(a[1]), "r"(a[2]), "r"(a[3]), "r"(b0), "r"(b1));
}

// SMEM layout for conv kernel (dynamic)
#define OFF_AH   0
#define OFF_AL   16384
#define OFF_BH   32768
#define OFF_BL   40960
#define OFF_IIDX 49152
#define OFF_OIDX 49664
#define SMEM_BYTES 50176

// ================= kernels =================

__global__ void zero_kernel(int total4)
{
    const float4 z = make_float4(0.f, 0.f, 0.f, 0.f);
    int i = blockIdx.x * blockDim.x + threadIdx.x;
    for (int j = i; j < total4; j += gridDim.x * blockDim.x) {
        reinterpret_cast<float4*>(g_buf1)[j] = z;
        reinterpret_cast<float4*>(g_buf2)[j] = z;
    }
    if (blockIdx.x == 0 && threadIdx.x < 64)
        reinterpret_cast<float4*>(g_stats)[threadIdx.x] = z;
}

// W[k][cin][cout] fp32 -> bf16 hi/lo split packed in mma B-fragment order,
// with output columns PERMUTED so each lane's 4 accumulator values from an
// (even,odd) nt-tile pair hit 4 contiguous global columns (enables red.v4).
// u32 index i: reg = i&1, lane = (i>>1)&31, nt = (i>>6)&7, ks = i>>9
// k0 = ks*16 + (lane&3)*2 + reg*8 ; local col l = lane>>2
// source col n = 16*(nt>>1) + 4*(l>>1) + 2*(nt&1) + (l&1)
__global__ __launch_bounds__(256)
void prep_w_kernel(const float* __restrict__ W1, const float* __restrict__ W2, int K)
{
    const int k     = blockIdx.x;
    const int layer = blockIdx.y;
    const float* Wk = (layer ? W2 : W1) + (size_t)k * 4096;
    uint32_t* dh = (layer ? g_WfH2 : g_WfH1) + (size_t)k * 2048;
    uint32_t* dl = (layer ? g_WfL2 : g_WfL1) + (size_t)k * 2048;

    for (int i = threadIdx.x; i < 2048; i += 256) {
        const int reg  = i & 1;
        const int lane = (i >> 1) & 31;
        const int nt   = (i >> 6) & 7;
        const int ks   = i >> 9;
        const int k0   = ks * 16 + (lane & 3) * 2 + reg * 8;
        const int l    = lane >> 2;
        const int n    = 16 * (nt >> 1) + 4 * (l >> 1) + 2 * (nt & 1) + (l & 1);
        const float v0 = Wk[k0 * 64 + n];
        const float v1 = Wk[(k0 + 1) * 64 + n];
        const __nv_bfloat16 h0 = __float2bfloat16(v0);
        const __nv_bfloat16 h1 = __float2bfloat16(v1);
        const __nv_bfloat16 l0 = __float2bfloat16(v0 - __bfloat162float(h0));
        const __nv_bfloat16 l1 = __float2bfloat16(v1 - __bfloat162float(h1));
        dh[i] = (uint32_t)__bfloat16_as_ushort(h0)
              | ((uint32_t)__bfloat16_as_ushort(h1) << 16);
        dl[i] = (uint32_t)__bfloat16_as_ushort(l0)
              | ((uint32_t)__bfloat16_as_ushort(l1) << 16);
    }
}

// fp32 rows -> bf16 hi/lo split (optionally fused relu(bn) via sb scale/shift)
__global__ __launch_bounds__(256)
void prep_feat_kernel(const float* __restrict__ src, const float* __restrict__ sb,
                      int N)
{
    const int gid = blockIdx.x * blockDim.x + threadIdx.x;
    if (gid >= N * 8) return;
    const int row = gid >> 3;
    const int c0  = (gid & 7) * 8;

    const float4 v0 = reinterpret_cast<const float4*>(src + (size_t)row * 64 + c0)[0];
    const float4 v1 = reinterpret_cast<const float4*>(src + (size_t)row * 64 + c0)[1];
    float v[8] = {v0.x, v0.y, v0.z, v0.w, v1.x, v1.y, v1.z, v1.w};

    if (sb) {
        #pragma unroll
        for (int j = 0; j < 8; ++j)
            v[j] = fmaxf(fmaf(v[j], sb[c0 + j], sb[64 + c0 + j]), 0.f);
    }

    union { __nv_bfloat16 h[8]; uint4 u; } uh, ul;
    #pragma unroll
    for (int j = 0; j < 8; ++j) {
        const __nv_bfloat16 hi = __float2bfloat16(v[j]);
        uh.h[j] = hi;
        ul.h[j] = __float2bfloat16(v[j] - __bfloat162float(hi));
    }
    reinterpret_cast<uint4*>(g_fhi)[(size_t)row * 8 + (c0 >> 3)] = uh.u;
    reinterpret_cast<uint4*>(g_flo)[(size_t)row * 8 + (c0 >> 3)] = ul.u;
}

// gather -> mma.sync bf16-split -> red.v4 scatter
// 8 warps arranged 4(row)x2(col); each warp: 32 rows x 32 cols.
// B-fragment LDS per block: 64KB (vs 128KB with 1-D row tiling), A: 64KB.
__global__ __launch_bounds__(256)
void conv_mma_kernel(const __nv_bfloat16* __restrict__ fhi,
                     const __nv_bfloat16* __restrict__ flo,
                     const uint32_t* __restrict__ WfH,
                     const uint32_t* __restrict__ WfL,
                     const int* __restrict__ in_maps,
                     const int* __restrict__ out_maps,
                     float* __restrict__ out,
                     int M)
{
    extern __shared__ char sm[];
    char*     Ah   = sm + OFF_AH;
    char*     Al   = sm + OFF_AL;
    uint32_t* BH   = reinterpret_cast<uint32_t*>(sm + OFF_BH);
    uint32_t* BL   = reinterpret_cast<uint32_t*>(sm + OFF_BL);
    int*      iidx = reinterpret_cast<int*>(sm + OFF_IIDX);
    int*      oidx = reinterpret_cast<int*>(sm + OFF_OIDX);

    const int t    = threadIdx.x;
    const int lane = t & 31;
    const int w    = t >> 5;
    const int wr   = w >> 1;      // row group 0..3
    const int wc   = w & 1;       // col group 0..1
    const int k    = blockIdx.y;
    const int m0   = blockIdx.x * 128;

    // maps
    if (t < 128) {
        const int m = m0 + t;
        iidx[t] = (m < M) ? in_maps [(size_t)k * M + m] : -1;
        oidx[t] = (m < M) ? out_maps[(size_t)k * M + m] : -1;
    }
    // B-fragment copy (1024 uint4 total across hi+lo)
    {
        const uint4* sh = reinterpret_cast<const uint4*>(WfH + (size_t)k * 2048);
        const uint4* sl = reinterpret_cast<const uint4*>(WfL + (size_t)k * 2048);
        reinterpret_cast<uint4*>(BH)[t]       = sh[t];
        reinterpret_cast<uint4*>(BH)[t + 256] = sh[t + 256];
        reinterpret_cast<uint4*>(BL)[t]       = sl[t];
        reinterpret_cast<uint4*>(BL)[t + 256] = sl[t + 256];
    }
    __syncthreads();

    // gather A (hi/lo): 2 threads per row, 4 chunks each; XOR-swizzle c^(row&7)
    {
        const int row = t >> 1;
        const int cb  = (t & 1) * 4;
        const int src = iidx[row];
        const uint4 z = make_uint4(0, 0, 0, 0);
        #pragma unroll
        for (int i = 0; i < 4; ++i) {
            const int c = cb + i;
            uint4 vh = z, vl = z;
            if (src >= 0) {
                vh = reinterpret_cast<const uint4*>(fhi)[(size_t)src * 8 + c];
                vl = reinterpret_cast<const uint4*>(flo)[(size_t)src * 8 + c];
            }
            const int d = row * 128 + ((c ^ (row & 7)) << 4);
            *reinterpret_cast<uint4*>(Ah + d) = vh;
            *reinterpret_cast<uint4*>(Al + d) = vl;
        }
    }
    __syncthreads();

    // MMA mainloop: warp covers rows [wr*32, wr*32+32), cols [wc*32, wc*32+32)
    float acc[2][4][4];
    #pragma unroll
    for (int rt = 0; rt < 2; ++rt)
        #pragma unroll
        for (int nl = 0; nl < 4; ++nl)
            #pragma unroll
            for (int j = 0; j < 4; ++j) acc[rt][nl][j] = 0.f;

    const uint32_t ahb = smem_u32(Ah);
    const uint32_t alb = smem_u32(Al);
    const int half = lane >> 4;

    #pragma unroll
    for (int ks = 0; ks < 4; ++ks) {
        uint32_t aH[2][4], aL[2][4];
        #pragma unroll
        for (int rt = 0; rt < 2; ++rt) {
            const int row   = wr * 32 + rt * 16 + (lane & 15);
            const int chunk = ks * 2 + half;
            const uint32_t off = row * 128 + ((chunk ^ (row & 7)) << 4);
            ldmatrix_x4(aH[rt], ahb + off);
            ldmatrix_x4(aL[rt], alb + off);
        }
        #pragma unroll
        for (int nl = 0; nl < 4; ++nl) {
            const int nt = wc * 4 + nl;
            const int fi = ((ks * 8 + nt) * 32 + lane) * 2;
            const uint2 bh = *reinterpret_cast<const uint2*>(&BH[fi]);
            const uint2 bl = *reinterpret_cast<const uint2*>(&BL[fi]);
            #pragma unroll
            for (int rt = 0; rt < 2; ++rt) {
                mma16816(acc[rt][nl], aH[rt], bh.x, bh.y);
                mma16816(acc[rt][nl], aH[rt], bl.x, bl.y);
                mma16816(acc[rt][nl], aL[rt], bh.x, bh.y);
            }
        }
    }

    // scatter via red.v4: permuted cols -> pair (2p,2p+1) lands contiguously
    // global pair gp = wc*2 + p, col base 16*gp + 4*(lane&3)
    #pragma unroll
    for (int rt = 0; rt < 2; ++rt) {
        const int r0 = wr * 32 + rt * 16 + (lane >> 2);
        const int o0 = oidx[r0];
        const int o1 = oidx[r0 + 8];
        const int cb = 4 * (lane & 3);
        #pragma unroll
        for (int p = 0; p < 2; ++p) {
            const int col = 16 * (wc * 2 + p) + cb;
            if (o0 >= 0) {
                asm volatile("red.global.add.v4.f32 [%0], {%1, %2, %3, %4};"
                    :: "l"(out + (size_t)o0 * 64 + col),
                       "f"(acc[rt][2*p][0]), "f"(acc[rt][2*p][1]),
                       "f"(acc[rt][2*p+1][0]), "f"(acc[rt][2*p+1][1]) : "memory");
            }
            if (o1 >= 0) {
                asm volatile("red.global.add.v4.f32 [%0], {%1, %2, %3, %4};"
                    :: "l"(out + (size_t)o1 * 64 + col),
                       "f"(acc[rt][2*p][2]), "f"(acc[rt][2*p][3]),
                       "f"(acc[rt][2*p+1][2]), "f"(acc[rt][2*p+1][3]) : "memory");
            }
        }
    }
}

// per-channel sum / sumsq
__global__ __launch_bounds__(256)
void stats_kernel(const float* __restrict__ x, int N, float* __restrict__ sums)
{
    const int t   = threadIdx.x;
    const int col = t & 63;
    const int rg  = t >> 6;
    float s = 0.f, ss = 0.f;
    for (int r = blockIdx.x * 4 + rg; r < N; r += gridDim.x * 4) {
        const float v = x[(size_t)r * 64 + col];
        s += v; ss += v * v;
    }
    __shared__ float sh[512];
    sh[t] = s; sh[256 + t] = ss;
    __syncthreads();
    if (t < 64) {
        float S  = sh[t]       + sh[t + 64]       + sh[t + 128]       + sh[t + 192];
        float SS = sh[256 + t] + sh[256 + t + 64] + sh[256 + t + 128] + sh[256 + t + 192];
        atomicAdd(&sums[t],      S);
        atomicAdd(&sums[64 + t], SS);
    }
}

__global__ void finalize_kernel(const float* __restrict__ sums,
                                const float* __restrict__ gamma,
                                const float* __restrict__ beta,
                                float invN, float* __restrict__ sb)
{
    const int t = threadIdx.x;
    const float mean = sums[t] * invN;
    const float var  = fmaxf(sums[64 + t] * invN - mean * mean, 0.f);
    const float s    = gamma[t] * rsqrtf(var + EPSV);
    sb[t]      = s;
    sb[64 + t] = beta[t] - mean * s;
}

__global__ __launch_bounds__(256)
void final_kernel(const float* __restrict__ conv2, const float* __restrict__ sb2,
                  const float* __restrict__ feat, float* __restrict__ out, int n4)
{
    int i = blockIdx.x * blockDim.x + threadIdx.x;
    for (int j = i; j < n4; j += gridDim.x * blockDim.x) {
        const float4 v = reinterpret_cast<const float4*>(conv2)[j];
        const float4 f = reinterpret_cast<const float4*>(feat)[j];
        const int c0 = (j & 15) * 4;
        float4 r;
        r.x = fmaxf(fmaf(v.x, sb2[c0 + 0], sb2[64 + c0 + 0]) + f.x, 0.f);
        r.y = fmaxf(fmaf(v.y, sb2[c0 + 1], sb2[64 + c0 + 1]) + f.y, 0.f);
        r.z = fmaxf(fmaf(v.z, sb2[c0 + 2], sb2[64 + c0 + 2]) + f.z, 0.f);
        r.w = fmaxf(fmaf(v.w, sb2[c0 + 3], sb2[64 + c0 + 3]) + f.w, 0.f);
        reinterpret_cast<float4*>(out)[j] = r;
    }
}

// ================= launcher =================
extern "C" void kernel_launch(void* const* d_in, const int* in_sizes, int n_in,
                              void* d_out, int out_size)
{
    const float* features = (const float*)d_in[0];
    const float* W1       = (const float*)d_in[1];
    const float* gamma1   = (const float*)d_in[2];
    const float* beta1    = (const float*)d_in[3];
    const float* W2       = (const float*)d_in[4];
    const float* gamma2   = (const float*)d_in[5];
    const float* beta2    = (const float*)d_in[6];
    const int*   in_maps  = (const int*)d_in[7];
    const int*   out_maps = (const int*)d_in[8];
    float*       out      = (float*)d_out;

    const int N = in_sizes[0] / CH;
    const int K = in_sizes[1] / (CH * CH);
    const int M = in_sizes[7] / K;

    float* buf1;  cudaGetSymbolAddress((void**)&buf1,  g_buf1);
    float* buf2;  cudaGetSymbolAddress((void**)&buf2,  g_buf2);
    float* stats; cudaGetSymbolAddress((void**)&stats, g_stats);
    float* sb;    cudaGetSymbolAddress((void**)&sb,    g_sb);
    __nv_bfloat16 *fhi, *flo;
    cudaGetSymbolAddress((void**)&fhi, g_fhi);
    cudaGetSymbolAddress((void**)&flo, g_flo);
    uint32_t *wh1, *wl1, *wh2, *wl2;
    cudaGetSymbolAddress((void**)&wh1, g_WfH1);
    cudaGetSymbolAddress((void**)&wl1, g_WfL1);
    cudaGetSymbolAddress((void**)&wh2, g_WfH2);
    cudaGetSymbolAddress((void**)&wl2, g_WfL2);

    cudaFuncSetAttribute(conv_mma_kernel,
                         cudaFuncAttributeMaxDynamicSharedMemorySize, SMEM_BYTES);

    const int total4 = N * (CH / 4);
    const float invN = 1.0f / (float)N;
    const dim3 convGrid((M + 127) / 128, K);
    const int pfBlocks = (N * 8 + 255) / 256;

    zero_kernel<<<1024, 256>>>(total4);
    prep_w_kernel<<<dim3(K, 2), 256>>>(W1, W2, K);

    // conv1
    prep_feat_kernel<<<pfBlocks, 256>>>(features, nullptr, N);
    conv_mma_kernel<<<convGrid, 256, SMEM_BYTES>>>(fhi, flo, wh1, wl1,
                                                   in_maps, out_maps, buf1, M);
    stats_kernel<<<512, 256>>>(buf1, N, stats);
    finalize_kernel<<<1, 64>>>(stats, gamma1, beta1, invN, sb);

    // conv2 (BN1+ReLU fused into split pass)
    prep_feat_kernel<<<pfBlocks, 256>>>(buf1, sb, N);
    conv_mma_kernel<<<convGrid, 256, SMEM_BYTES>>>(fhi, flo, wh2, wl2,
                                                   in_maps, out_maps, buf2, M);
    stats_kernel<<<512, 256>>>(buf2, N, stats + 128);
    finalize_kernel<<<1, 64>>>(stats + 128, gamma2, beta2, invN, sb + 128);

    final_kernel<<<1024, 256>>>(buf2, sb + 128, features, out, total4);
}

// round 6
// speedup vs baseline: 1.5826x; 1.1171x over previous
#include <cuda_runtime.h>
#include <cuda_bf16.h>
#include <cstdint>

#define CH    64
#define EPSV  1e-5f
#define MAXN  100000
#define MAXK  27

// ================= scratch (__device__ globals, alloc-free) =================
__device__ float g_buf1[MAXN * CH];      // conv1 raw output (fp32)
__device__ float g_buf2[MAXN * CH];      // conv2 raw output (fp32)
__device__ float g_stats[256];           // [sum1, sumsq1, sum2, sumsq2]
__device__ float g_sb[256];              // [scale1, shift1, scale2, shift2]
__device__ __align__(16) __nv_bfloat16 g_fhi[MAXN * CH];
__device__ __align__(16) __nv_bfloat16 g_flo[MAXN * CH];
// W pre-packed into mma.sync B-fragment order (column-permuted): [k][2048] u32
__device__ __align__(16) uint32_t g_WfH1[MAXK * 2048];
__device__ __align__(16) uint32_t g_WfL1[MAXK * 2048];
__device__ __align__(16) uint32_t g_WfH2[MAXK * 2048];
__device__ __align__(16) uint32_t g_WfL2[MAXK * 2048];

// ================= helpers =================
__device__ __forceinline__ uint32_t smem_u32(const void* p) {
    uint32_t a;
    asm("{ .reg .u64 t; cvta.to.shared.u64 t, %1; cvt.u32.u64 %0, t; }" : "=r"(a) : "l"(p));
    return a;
}

__device__ __forceinline__ void ldmatrix_x4(uint32_t* r, uint32_t addr) {
    asm volatile("ldmatrix.sync.aligned.m8n8.x4.shared.b16 {%0,%1,%2,%3}, [%4];"
                 : "=r"(r[0]), "=r"(r[1]), "=r"(r[2]), "=r"(r[3]) : "r"(addr));
}

__device__ __forceinline__ void mma16816(float* c, const uint32_t* a,
                                         uint32_t b0, uint32_t b1) {
    asm volatile(
        "mma.sync.aligned.m16n8k16.row.col.f32.bf16.bf16.f32 "
        "{%0,%1,%2,%3}, {%4,%5,%6,%7}, {%8,%9}, {%0,%1,%2,%3};"
        : "+f"(c[0]), "+f"(c[1]), "+f"(c[2]), "+f"(c[3])
        : "r"(a[0]), "r"(a[1]), "r"(a[2]), "r"(a[3]), "r"(b0), "r"(b1));
}

// SMEM layout for conv kernel (dynamic)
#define OFF_AH   0
#define OFF_AL   16384
#define OFF_BH   32768
#define OFF_BL   40960
#define OFF_IIDX 49152
#define OFF_OIDX 49664
#define SMEM_BYTES 50176

// ================= kernels =================

__global__ void zero_kernel(int total4)
{
    const float4 z = make_float4(0.f, 0.f, 0.f, 0.f);
    int i = blockIdx.x * blockDim.x + threadIdx.x;
    for (int j = i; j < total4; j += gridDim.x * blockDim.x) {
        reinterpret_cast<float4*>(g_buf1)[j] = z;
        reinterpret_cast<float4*>(g_buf2)[j] = z;
    }
    if (blockIdx.x == 0 && threadIdx.x < 64)
        reinterpret_cast<float4*>(g_stats)[threadIdx.x] = z;
}

// W[k][cin][cout] fp32 -> bf16 hi/lo split packed in mma B-fragment order,
// with output columns PERMUTED so each lane's 4 accumulator values from an
// (even,odd) nt-tile pair hit 4 contiguous global columns (enables red.v4).
// u32 index i: reg = i&1, lane = (i>>1)&31, nt = (i>>6)&7, ks = i>>9
// k0 = ks*16 + (lane&3)*2 + reg*8 ; local col l = lane>>2
// source col n = 16*(nt>>1) + 4*(l>>1) + 2*(nt&1) + (l&1)
__global__ __launch_bounds__(256)
void prep_w_kernel(const float* __restrict__ W1, const float* __restrict__ W2, int K)
{
    const int k     = blockIdx.x;
    const int layer = blockIdx.y;
    const float* Wk = (layer ? W2 : W1) + (size_t)k * 4096;
    uint32_t* dh = (layer ? g_WfH2 : g_WfH1) + (size_t)k * 2048;
    uint32_t* dl = (layer ? g_WfL2 : g_WfL1) + (size_t)k * 2048;

    for (int i = threadIdx.x; i < 2048; i += 256) {
        const int reg  = i & 1;
        const int lane = (i >> 1) & 31;
        const int nt   = (i >> 6) & 7;
        const int ks   = i >> 9;
        const int k0   = ks * 16 + (lane & 3) * 2 + reg * 8;
        const int l    = lane >> 2;
        const int n    = 16 * (nt >> 1) + 4 * (l >> 1) + 2 * (nt & 1) + (l & 1);
        const float v0 = Wk[k0 * 64 + n];
        const float v1 = Wk[(k0 + 1) * 64 + n];
        const __nv_bfloat16 h0 = __float2bfloat16(v0);
        const __nv_bfloat16 h1 = __float2bfloat16(v1);
        const __nv_bfloat16 l0 = __float2bfloat16(v0 - __bfloat162float(h0));
        const __nv_bfloat16 l1 = __float2bfloat16(v1 - __bfloat162float(h1));
        dh[i] = (uint32_t)__bfloat16_as_ushort(h0)
              | ((uint32_t)__bfloat16_as_ushort(h1) << 16);
        dl[i] = (uint32_t)__bfloat16_as_ushort(l0)
              | ((uint32_t)__bfloat16_as_ushort(l1) << 16);
    }
}

// fp32 rows -> bf16 hi/lo split (optionally fused relu(bn) via sb scale/shift)
__global__ __launch_bounds__(256)
void prep_feat_kernel(const float* __restrict__ src, const float* __restrict__ sb,
                      int N)
{
    const int gid = blockIdx.x * blockDim.x + threadIdx.x;
    if (gid >= N * 8) return;
    const int row = gid >> 3;
    const int c0  = (gid & 7) * 8;

    const float4 v0 = reinterpret_cast<const float4*>(src + (size_t)row * 64 + c0)[0];
    const float4 v1 = reinterpret_cast<const float4*>(src + (size_t)row * 64 + c0)[1];
    float v[8] = {v0.x, v0.y, v0.z, v0.w, v1.x, v1.y, v1.z, v1.w};

    if (sb) {
        #pragma unroll
        for (int j = 0; j < 8; ++j)
            v[j] = fmaxf(fmaf(v[j], sb[c0 + j], sb[64 + c0 + j]), 0.f);
    }

    union { __nv_bfloat16 h[8]; uint4 u; } uh, ul;
    #pragma unroll
    for (int j = 0; j < 8; ++j) {
        const __nv_bfloat16 hi = __float2bfloat16(v[j]);
        uh.h[j] = hi;
        ul.h[j] = __float2bfloat16(v[j] - __bfloat162float(hi));
    }
    reinterpret_cast<uint4*>(g_fhi)[(size_t)row * 8 + (c0 >> 3)] = uh.u;
    reinterpret_cast<uint4*>(g_flo)[(size_t)row * 8 + (c0 >> 3)] = ul.u;
}

// gather -> mma.sync bf16-split -> red.v4 scatter
// 8 warps arranged 4(row)x2(col); each warp: 32 rows x 32 cols.
// Gather: 8 lanes per row (full 128B row per 8 lanes) -> 4 cache lines per
// warp instruction instead of 16 scattered sectors.
__global__ __launch_bounds__(256)
void conv_mma_kernel(const __nv_bfloat16* __restrict__ fhi,
                     const __nv_bfloat16* __restrict__ flo,
                     const uint32_t* __restrict__ WfH,
                     const uint32_t* __restrict__ WfL,
                     const int* __restrict__ in_maps,
                     const int* __restrict__ out_maps,
                     float* __restrict__ out,
                     int M)
{
    extern __shared__ char sm[];
    char*     Ah   = sm + OFF_AH;
    char*     Al   = sm + OFF_AL;
    uint32_t* BH   = reinterpret_cast<uint32_t*>(sm + OFF_BH);
    uint32_t* BL   = reinterpret_cast<uint32_t*>(sm + OFF_BL);
    int*      iidx = reinterpret_cast<int*>(sm + OFF_IIDX);
    int*      oidx = reinterpret_cast<int*>(sm + OFF_OIDX);

    const int t    = threadIdx.x;
    const int lane = t & 31;
    const int w    = t >> 5;
    const int wr   = w >> 1;      // row group 0..3
    const int wc   = w & 1;       // col group 0..1
    const int k    = blockIdx.y;
    const int m0   = blockIdx.x * 128;

    // maps
    if (t < 128) {
        const int m = m0 + t;
        iidx[t] = (m < M) ? in_maps [(size_t)k * M + m] : -1;
        oidx[t] = (m < M) ? out_maps[(size_t)k * M + m] : -1;
    }
    // B-fragment copy (1024 uint4 total across hi+lo)
    {
        const uint4* sh = reinterpret_cast<const uint4*>(WfH + (size_t)k * 2048);
        const uint4* sl = reinterpret_cast<const uint4*>(WfL + (size_t)k * 2048);
        reinterpret_cast<uint4*>(BH)[t]       = sh[t];
        reinterpret_cast<uint4*>(BH)[t + 256] = sh[t + 256];
        reinterpret_cast<uint4*>(BL)[t]       = sl[t];
        reinterpret_cast<uint4*>(BL)[t + 256] = sl[t + 256];
    }
    __syncthreads();

    // gather A (hi/lo): 8 lanes per row, one 16B chunk each.
    // Warp covers 4 full rows per instruction -> 4 cache lines (coalesced).
    {
        const int c = t & 7;          // chunk 0..7
        const int g = t >> 3;         // row sub-index 0..31
        const uint4 z = make_uint4(0, 0, 0, 0);
        #pragma unroll
        for (int it = 0; it < 4; ++it) {
            const int row = it * 32 + g;
            const int src = iidx[row];
            uint4 vh = z, vl = z;
            if (src >= 0) {
                vh = reinterpret_cast<const uint4*>(fhi)[(size_t)src * 8 + c];
                vl = reinterpret_cast<const uint4*>(flo)[(size_t)src * 8 + c];
            }
            const int d = row * 128 + ((c ^ (row & 7)) << 4);
            *reinterpret_cast<uint4*>(Ah + d) = vh;
            *reinterpret_cast<uint4*>(Al + d) = vl;
        }
    }
    __syncthreads();

    // MMA mainloop: warp covers rows [wr*32, wr*32+32), cols [wc*32, wc*32+32)
    float acc[2][4][4];
    #pragma unroll
    for (int rt = 0; rt < 2; ++rt)
        #pragma unroll
        for (int nl = 0; nl < 4; ++nl)
            #pragma unroll
            for (int j = 0; j < 4; ++j) acc[rt][nl][j] = 0.f;

    const uint32_t ahb = smem_u32(Ah);
    const uint32_t alb = smem_u32(Al);
    const int half = lane >> 4;

    #pragma unroll
    for (int ks = 0; ks < 4; ++ks) {
        uint32_t aH[2][4], aL[2][4];
        #pragma unroll
        for (int rt = 0; rt < 2; ++rt) {
            const int row   = wr * 32 + rt * 16 + (lane & 15);
            const int chunk = ks * 2 + half;
            const uint32_t off = row * 128 + ((chunk ^ (row & 7)) << 4);
            ldmatrix_x4(aH[rt], ahb + off);
            ldmatrix_x4(aL[rt], alb + off);
        }
        #pragma unroll
        for (int nl = 0; nl < 4; ++nl) {
            const int nt = wc * 4 + nl;
            const int fi = ((ks * 8 + nt) * 32 + lane) * 2;
            const uint2 bh = *reinterpret_cast<const uint2*>(&BH[fi]);
            const uint2 bl = *reinterpret_cast<const uint2*>(&BL[fi]);
            #pragma unroll
            for (int rt = 0; rt < 2; ++rt) {
                mma16816(acc[rt][nl], aH[rt], bh.x, bh.y);
                mma16816(acc[rt][nl], aH[rt], bl.x, bl.y);
                mma16816(acc[rt][nl], aL[rt], bh.x, bh.y);
            }
        }
    }

    // scatter via red.v4: permuted cols -> pair (2p,2p+1) lands contiguously
    // global pair gp = wc*2 + p, col base 16*gp + 4*(lane&3)
    #pragma unroll
    for (int rt = 0; rt < 2; ++rt) {
        const int r0 = wr * 32 + rt * 16 + (lane >> 2);
        const int o0 = oidx[r0];
        const int o1 = oidx[r0 + 8];
        const int cb = 4 * (lane & 3);
        #pragma unroll
        for (int p = 0; p < 2; ++p) {
            const int col = 16 * (wc * 2 + p) + cb;
            if (o0 >= 0) {
                asm volatile("red.global.add.v4.f32 [%0], {%1, %2, %3, %4};"
                    :: "l"(out + (size_t)o0 * 64 + col),
                       "f"(acc[rt][2*p][0]), "f"(acc[rt][2*p][1]),
                       "f"(acc[rt][2*p+1][0]), "f"(acc[rt][2*p+1][1]) : "memory");
            }
            if (o1 >= 0) {
                asm volatile("red.global.add.v4.f32 [%0], {%1, %2, %3, %4};"
                    :: "l"(out + (size_t)o1 * 64 + col),
                       "f"(acc[rt][2*p][2]), "f"(acc[rt][2*p][3]),
                       "f"(acc[rt][2*p+1][2]), "f"(acc[rt][2*p+1][3]) : "memory");
            }
        }
    }
}

// per-channel sum / sumsq
__global__ __launch_bounds__(256)
void stats_kernel(const float* __restrict__ x, int N, float* __restrict__ sums)
{
    const int t   = threadIdx.x;
    const int col = t & 63;
    const int rg  = t >> 6;
    float s = 0.f, ss = 0.f;
    for (int r = blockIdx.x * 4 + rg; r < N; r += gridDim.x * 4) {
        const float v = x[(size_t)r * 64 + col];
        s += v; ss += v * v;
    }
    __shared__ float sh[512];
    sh[t] = s; sh[256 + t] = ss;
    __syncthreads();
    if (t < 64) {
        float S  = sh[t]       + sh[t + 64]       + sh[t + 128]       + sh[t + 192];
        float SS = sh[256 + t] + sh[256 + t + 64] + sh[256 + t + 128] + sh[256 + t + 192];
        atomicAdd(&sums[t],      S);
        atomicAdd(&sums[64 + t], SS);
    }
}

__global__ void finalize_kernel(const float* __restrict__ sums,
                                const float* __restrict__ gamma,
                                const float* __restrict__ beta,
                                float invN, float* __restrict__ sb)
{
    const int t = threadIdx.x;
    const float mean = sums[t] * invN;
    const float var  = fmaxf(sums[64 + t] * invN - mean * mean, 0.f);
    const float s    = gamma[t] * rsqrtf(var + EPSV);
    sb[t]      = s;
    sb[64 + t] = beta[t] - mean * s;
}

__global__ __launch_bounds__(256)
void final_kernel(const float* __restrict__ conv2, const float* __restrict__ sb2,
                  const float* __restrict__ feat, float* __restrict__ out, int n4)
{
    int i = blockIdx.x * blockDim.x + threadIdx.x;
    for (int j = i; j < n4; j += gridDim.x * blockDim.x) {
        const float4 v = reinterpret_cast<const float4*>(conv2)[j];
        const float4 f = reinterpret_cast<const float4*>(feat)[j];
        const int c0 = (j & 15) * 4;
        float4 r;
        r.x = fmaxf(fmaf(v.x, sb2[c0 + 0], sb2[64 + c0 + 0]) + f.x, 0.f);
        r.y = fmaxf(fmaf(v.y, sb2[c0 + 1], sb2[64 + c0 + 1]) + f.y, 0.f);
        r.z = fmaxf(fmaf(v.z, sb2[c0 + 2], sb2[64 + c0 + 2]) + f.z, 0.f);
        r.w = fmaxf(fmaf(v.w, sb2[c0 + 3], sb2[64 + c0 + 3]) + f.w, 0.f);
        reinterpret_cast<float4*>(out)[j] = r;
    }
}

// ================= launcher =================
extern "C" void kernel_launch(void* const* d_in, const int* in_sizes, int n_in,
                              void* d_out, int out_size)
{
    const float* features = (const float*)d_in[0];
    const float* W1       = (const float*)d_in[1];
    const float* gamma1   = (const float*)d_in[2];
    const float* beta1    = (const float*)d_in[3];
    const float* W2       = (const float*)d_in[4];
    const float* gamma2   = (const float*)d_in[5];
    const float* beta2    = (const float*)d_in[6];
    const int*   in_maps  = (const int*)d_in[7];
    const int*   out_maps = (const int*)d_in[8];
    float*       out      = (float*)d_out;

    const int N = in_sizes[0] / CH;
    const int K = in_sizes[1] / (CH * CH);
    const int M = in_sizes[7] / K;

    float* buf1;  cudaGetSymbolAddress((void**)&buf1,  g_buf1);
    float* buf2;  cudaGetSymbolAddress((void**)&buf2,  g_buf2);
    float* stats; cudaGetSymbolAddress((void**)&stats, g_stats);
    float* sb;    cudaGetSymbolAddress((void**)&sb,    g_sb);
    __nv_bfloat16 *fhi, *flo;
    cudaGetSymbolAddress((void**)&fhi, g_fhi);
    cudaGetSymbolAddress((void**)&flo, g_flo);
    uint32_t *wh1, *wl1, *wh2, *wl2;
    cudaGetSymbolAddress((void**)&wh1, g_WfH1);
    cudaGetSymbolAddress((void**)&wl1, g_WfL1);
    cudaGetSymbolAddress((void**)&wh2, g_WfH2);
    cudaGetSymbolAddress((void**)&wl2, g_WfL2);

    cudaFuncSetAttribute(conv_mma_kernel,
                         cudaFuncAttributeMaxDynamicSharedMemorySize, SMEM_BYTES);

    const int total4 = N * (CH / 4);
    const float invN = 1.0f / (float)N;
    const dim3 convGrid((M + 127) / 128, K);
    const int pfBlocks = (N * 8 + 255) / 256;

    zero_kernel<<<1024, 256>>>(total4);
    prep_w_kernel<<<dim3(K, 2), 256>>>(W1, W2, K);

    // conv1
    prep_feat_kernel<<<pfBlocks, 256>>>(features, nullptr, N);
    conv_mma_kernel<<<convGrid, 256, SMEM_BYTES>>>(fhi, flo, wh1, wl1,
                                                   in_maps, out_maps, buf1, M);
    stats_kernel<<<512, 256>>>(buf1, N, stats);
    finalize_kernel<<<1, 64>>>(stats, gamma1, beta1, invN, sb);

    // conv2 (BN1+ReLU fused into split pass)
    prep_feat_kernel<<<pfBlocks, 256>>>(buf1, sb, N);
    conv_mma_kernel<<<convGrid, 256, SMEM_BYTES>>>(fhi, flo, wh2, wl2,
                                                   in_maps, out_maps, buf2, M);
    stats_kernel<<<512, 256>>>(buf2, N, stats + 128);
    finalize_kernel<<<1, 64>>>(stats + 128, gamma2, beta2, invN, sb + 128);

    final_kernel<<<1024, 256>>>(buf2, sb + 128, features, out, total4);
}